// round 9
// baseline (speedup 1.0000x reference)
#include <cuda_runtime.h>
#include <cuda_bf16.h>
#include <math.h>
#include <stdint.h>

#define D_MODEL 1024
#define D_MID   4096
#define NHEAD   16
#define HDIM    64
#define SEQ     2048
#define BATCH   2
#define NROWS   (BATCH * SEQ)      // 4096
#define LN_EPS  1e-5f

// -------------------- scratch (device globals, no allocation) --------------------
__device__ float g_nx  [NROWS * D_MODEL];
__device__ float g_qkv [NROWS * 3 * D_MODEL];
__device__ float g_ctx [NROWS * D_MODEL];
__device__ float g_x1  [NROWS * D_MODEL];
__device__ float g_h   [NROWS * D_MID];
// tf32-converted weights
__device__ float g_wqkv[D_MODEL * 3 * D_MODEL];
__device__ float g_wo  [D_MODEL * D_MODEL];
__device__ float g_w1  [D_MODEL * D_MID];
__device__ float g_w2  [D_MID * D_MODEL];

// -------------------- helpers --------------------
__device__ __forceinline__ float f2tf32(float f) {
    uint32_t r;
    asm("cvt.rna.tf32.f32 %0, %1;" : "=r"(r) : "f"(f));
    return __uint_as_float(r);
}

__device__ __forceinline__ void mma_tf32(
    float c[4], const uint32_t a[4], const uint32_t b[2])
{
    asm volatile(
        "mma.sync.aligned.m16n8k8.row.col.f32.tf32.tf32.f32 "
        "{%0,%1,%2,%3}, {%4,%5,%6,%7}, {%8,%9}, {%0,%1,%2,%3};"
        : "+f"(c[0]), "+f"(c[1]), "+f"(c[2]), "+f"(c[3])
        : "r"(a[0]), "r"(a[1]), "r"(a[2]), "r"(a[3]),
          "r"(b[0]), "r"(b[1]));
}

__device__ __forceinline__ void cp_async16(void* sptr, const void* gptr) {
    uint32_t s = (uint32_t)__cvta_generic_to_shared(sptr);
    asm volatile("cp.async.cg.shared.global [%0], [%1], 16;" :: "r"(s), "l"(gptr));
}
#define CP_COMMIT() asm volatile("cp.async.commit_group;")
#define CP_WAIT(n)  asm volatile("cp.async.wait_group %0;" :: "n"(n))

__device__ __forceinline__ float gelu_f(float x) {
    float x3 = x * x * x;
    return 0.5f * x * (1.f + tanhf(0.7978845608028654f * (x + 0.044715f * x3)));
}

// -------------------- weight tf32 conversion (all 4 in one launch) --------------------
#define N4_QKV (D_MODEL * 3 * D_MODEL / 4)
#define N4_O   (D_MODEL * D_MODEL / 4)
#define N4_W1  (D_MODEL * D_MID / 4)
#define N4_W2  (D_MID * D_MODEL / 4)
#define N4_TOT (N4_QKV + N4_O + N4_W1 + N4_W2)

__global__ void __launch_bounds__(256) cvt_all_k(
    const float* __restrict__ wqkv, const float* __restrict__ wo,
    const float* __restrict__ w1,   const float* __restrict__ w2,
    float* __restrict__ oqkv, float* __restrict__ oo,
    float* __restrict__ o1,   float* __restrict__ o2)
{
    int i = blockIdx.x * blockDim.x + threadIdx.x;
    int stride = gridDim.x * blockDim.x;
    for (; i < N4_TOT; i += stride) {
        const float4* src; float4* dst; int idx;
        if (i < N4_QKV)                   { src = (const float4*)wqkv; dst = (float4*)oqkv; idx = i; }
        else if (i < N4_QKV + N4_O)       { src = (const float4*)wo;   dst = (float4*)oo;   idx = i - N4_QKV; }
        else if (i < N4_QKV + N4_O + N4_W1){ src = (const float4*)w1;  dst = (float4*)o1;   idx = i - N4_QKV - N4_O; }
        else                              { src = (const float4*)w2;   dst = (float4*)o2;   idx = i - N4_QKV - N4_O - N4_W1; }
        float4 v = src[idx];
        v.x = f2tf32(v.x); v.y = f2tf32(v.y);
        v.z = f2tf32(v.z); v.w = f2tf32(v.w);
        dst[idx] = v;
    }
}

// -------------------- LayerNorm (tf32-rounded output) --------------------
__global__ void __launch_bounds__(256) ln_kernel(
    const float* __restrict__ x, const float* __restrict__ g,
    const float* __restrict__ be, float* __restrict__ out)
{
    int row = blockIdx.x;
    int tid = threadIdx.x;
    const float4* xr = reinterpret_cast<const float4*>(x + (size_t)row * D_MODEL);
    float4 v = xr[tid];
    float s  = v.x + v.y + v.z + v.w;
    float ss = v.x*v.x + v.y*v.y + v.z*v.z + v.w*v.w;

    __shared__ float shs[8], shss[8];
    #pragma unroll
    for (int o = 16; o > 0; o >>= 1) {
        s  += __shfl_down_sync(0xffffffffu, s,  o);
        ss += __shfl_down_sync(0xffffffffu, ss, o);
    }
    int w = tid >> 5, lane = tid & 31;
    if (lane == 0) { shs[w] = s; shss[w] = ss; }
    __syncthreads();
    if (w == 0) {
        s  = (lane < 8) ? shs[lane]  : 0.f;
        ss = (lane < 8) ? shss[lane] : 0.f;
        #pragma unroll
        for (int o = 4; o > 0; o >>= 1) {
            s  += __shfl_down_sync(0xffffffffu, s,  o);
            ss += __shfl_down_sync(0xffffffffu, ss, o);
        }
        if (lane == 0) { shs[0] = s; shss[0] = ss; }
    }
    __syncthreads();
    float mu  = shs[0] * (1.f / D_MODEL);
    float var = shss[0] * (1.f / D_MODEL) - mu * mu;
    float rstd = rsqrtf(var + LN_EPS);

    float4 gv = reinterpret_cast<const float4*>(g)[tid];
    float4 bv = reinterpret_cast<const float4*>(be)[tid];
    float4 o4;
    o4.x = f2tf32((v.x - mu) * rstd * gv.x + bv.x);
    o4.y = f2tf32((v.y - mu) * rstd * gv.y + bv.y);
    o4.z = f2tf32((v.z - mu) * rstd * gv.z + bv.z);
    o4.w = f2tf32((v.w - mu) * rstd * gv.w + bv.w);
    reinterpret_cast<float4*>(out + (size_t)row * D_MODEL)[tid] = o4;
}

// -------------------- TF32 tensor-core GEMM, 4-stage cp.async --------------------
#define LDA 36
#define LDB 136
#define STAGES 4
#define SSZ (128 * LDA + 32 * LDB)

template<int EPI, int ROUND>
__global__ void __launch_bounds__(256) tgemm_k(
    const float* __restrict__ A, const float* __restrict__ B,
    const float* __restrict__ bias, const float* __restrict__ res,
    float* __restrict__ C, int M, int N, int K)
{
    extern __shared__ float smp[];

    const int bm = blockIdx.y * 128;
    const int bn = blockIdx.x * 128;
    const int tid  = threadIdx.x;
    const int wid  = tid >> 5;
    const int lane = tid & 31;
    const int gq = lane >> 2;
    const int tg = lane & 3;

    const int m0 = (wid & 3) * 32;
    const int n0 = (wid >> 2) * 64;

    const int nkt = K >> 5;

    auto issue = [&](int stage, int kt) {
        float* As = smp + stage * SSZ;
        float* Bs = As + 128 * LDA;
        const int ko = kt << 5;
        #pragma unroll
        for (int l = 0; l < 4; ++l) {
            int v = tid + l * 256;
            cp_async16(&As[(v >> 3) * LDA + ((v & 7) << 2)],
                       A + (size_t)(bm + (v >> 3)) * K + ko + ((v & 7) << 2));
            cp_async16(&Bs[(v >> 5) * LDB + ((v & 31) << 2)],
                       B + (size_t)(ko + (v >> 5)) * N + bn + ((v & 31) << 2));
        }
    };

    #pragma unroll
    for (int s = 0; s < STAGES - 1; ++s) { issue(s, s); CP_COMMIT(); }

    float acc[2][8][4];
    #pragma unroll
    for (int i = 0; i < 2; ++i)
        #pragma unroll
        for (int j = 0; j < 8; ++j)
            #pragma unroll
            for (int t = 0; t < 4; ++t) acc[i][j][t] = 0.f;

    for (int kt = 0; kt < nkt; ++kt) {
        CP_WAIT(2);
        __syncthreads();
        if (kt + STAGES - 1 < nkt) issue((kt + STAGES - 1) & 3, kt + STAGES - 1);
        CP_COMMIT();

        const float* As = smp + (kt & 3) * SSZ;
        const float* Bs = As + 128 * LDA;

        #pragma unroll
        for (int kk = 0; kk < 4; ++kk) {
            const int k = kk << 3;
            uint32_t afr[2][4], bfr[8][2];
            #pragma unroll
            for (int i = 0; i < 2; ++i) {
                int r = m0 + i * 16 + gq;
                int c = k + tg;
                afr[i][0] = __float_as_uint(As[r * LDA + c]);
                afr[i][1] = __float_as_uint(As[(r + 8) * LDA + c]);
                afr[i][2] = __float_as_uint(As[r * LDA + c + 4]);
                afr[i][3] = __float_as_uint(As[(r + 8) * LDA + c + 4]);
            }
            #pragma unroll
            for (int j = 0; j < 8; ++j) {
                int col = n0 + j * 8 + gq;
                int row = k + tg;
                bfr[j][0] = __float_as_uint(Bs[row * LDB + col]);
                bfr[j][1] = __float_as_uint(Bs[(row + 4) * LDB + col]);
            }
            #pragma unroll
            for (int i = 0; i < 2; ++i)
                #pragma unroll
                for (int j = 0; j < 8; ++j)
                    mma_tf32(acc[i][j], afr[i], bfr[j]);
        }
    }

    #pragma unroll
    for (int i = 0; i < 2; ++i) {
        #pragma unroll
        for (int half = 0; half < 2; ++half) {
            int m = bm + m0 + i * 16 + gq + half * 8;
            #pragma unroll
            for (int j = 0; j < 8; ++j) {
                int n = bn + n0 + j * 8 + 2 * tg;
                float c0 = acc[i][j][half * 2 + 0] + bias[n];
                float c1 = acc[i][j][half * 2 + 1] + bias[n + 1];
                if (EPI == 1) { c0 = gelu_f(c0); c1 = gelu_f(c1); }
                if (EPI == 2) {
                    const float2 r2 = *reinterpret_cast<const float2*>(res + (size_t)m * N + n);
                    c0 += r2.x; c1 += r2.y;
                }
                if (ROUND) { c0 = f2tf32(c0); c1 = f2tf32(c1); }
                float2 o2; o2.x = c0; o2.y = c1;
                *reinterpret_cast<float2*>(C + (size_t)m * N + n) = o2;
            }
        }
    }
}

// -------------------- Flash attention (causal, tf32, 512 threads, q-tile 256) --
// 16 warps; warp w owns q-rows [w*16, w*16+16) of the 256-row tile.
// kv-tile 64, double-buffered cp.async. Warp-level causal skip.
#define PQ 68
#define PV 72
#define KVSZ (64 * PQ + 64 * PV)
#define QTILE 256

__global__ void __launch_bounds__(512, 1) flash_attn_k(
    const float* __restrict__ qkv, float* __restrict__ ctx)
{
    extern __shared__ float sm[];
    float* Qs  = sm;                       // 256 x PQ
    float* KV0 = Qs + QTILE * PQ;          // 2 stages of (K 64xPQ, V 64xPV)
    float* Ss  = KV0 + 2 * KVSZ;           // 256 x PQ

    const int qt  = (gridDim.x - 1) - blockIdx.x;   // heavy blocks first
    const int h   = blockIdx.y;
    const int b   = blockIdx.z;
    const int tid = threadIdx.x;
    const int wid = tid >> 5;
    const int lane = tid & 31;
    const int gq = lane >> 2;
    const int tg = lane & 3;
    const int wbase = wid * 16;
    const float scale = 0.03125f;          // 1/sqrt(1024) = 2^-5 exact

    const size_t base = (size_t)b * SEQ * (3 * D_MODEL);
    const float* qp = qkv + base + h * HDIM;
    const float* kp = qkv + base + D_MODEL + h * HDIM;
    const float* vp = qkv + base + 2 * D_MODEL + h * HDIM;
    const int qbase = qt * QTILE;
    const int njt = 4 * (qt + 1);          // kv tiles of 64 covering [0, qbase+256)

    auto issue_kv = [&](int jt, int buf) {
        float* Ks = KV0 + buf * KVSZ;
        float* Vs = Ks + 64 * PQ;
        const int jb = jt * 64;
        #pragma unroll
        for (int l = 0; l < 2; ++l) {
            int v = tid + l * 512;
            int r = v >> 4, c4 = (v & 15) << 2;
            cp_async16(&Ks[r * PQ + c4], kp + (size_t)(jb + r) * (3 * D_MODEL) + c4);
            cp_async16(&Vs[r * PV + c4], vp + (size_t)(jb + r) * (3 * D_MODEL) + c4);
        }
    };

    // prologue: Q (256x64) + KV(0) in group 0
    #pragma unroll
    for (int l = 0; l < 8; ++l) {
        int v = tid + l * 512;
        int r = v >> 4, c4 = (v & 15) << 2;
        cp_async16(&Qs[r * PQ + c4], qp + (size_t)(qbase + r) * (3 * D_MODEL) + c4);
    }
    issue_kv(0, 0);
    CP_COMMIT();

    float o[8][4];
    #pragma unroll
    for (int j = 0; j < 8; ++j)
        #pragma unroll
        for (int t = 0; t < 4; ++t) o[j][t] = 0.f;
    float m0r = -INFINITY, m1r = -INFINITY;
    float l0r = 0.f, l1r = 0.f;

    for (int jt = 0; jt < njt; ++jt) {
        if (jt + 1 < njt) issue_kv(jt + 1, (jt + 1) & 1);
        CP_COMMIT();
        CP_WAIT(1);
        __syncthreads();

        const int jbase = jt * 64;
        // warp-level causal skip: kv tile entirely above this warp's rows
        const bool active = (jbase <= qbase + wbase + 15);

        if (active) {
            const float* Ks = KV0 + (jt & 1) * KVSZ;
            const float* Vs = Ks + 64 * PQ;

            // S = Q @ K^T : warp tile 16 x 64
            float s[8][4];
            #pragma unroll
            for (int j = 0; j < 8; ++j)
                #pragma unroll
                for (int t = 0; t < 4; ++t) s[j][t] = 0.f;

            #pragma unroll
            for (int kk = 0; kk < 8; ++kk) {
                const int k = kk << 3;
                uint32_t afr[4];
                const int r = wbase + gq;
                const int c = k + tg;
                afr[0] = __float_as_uint(Qs[r * PQ + c]);
                afr[1] = __float_as_uint(Qs[(r + 8) * PQ + c]);
                afr[2] = __float_as_uint(Qs[r * PQ + c + 4]);
                afr[3] = __float_as_uint(Qs[(r + 8) * PQ + c + 4]);
                #pragma unroll
                for (int j = 0; j < 8; ++j) {
                    uint32_t bfr[2];
                    bfr[0] = __float_as_uint(Ks[(j * 8 + gq) * PQ + c]);
                    bfr[1] = __float_as_uint(Ks[(j * 8 + gq) * PQ + c + 4]);
                    mma_tf32(s[j], afr, bfr);
                }
            }

            // scale
            #pragma unroll
            for (int j = 0; j < 8; ++j) {
                s[j][0] *= scale; s[j][1] *= scale;
                s[j][2] *= scale; s[j][3] *= scale;
            }

            // causal mask (tile overlaps this warp's diagonal)
            if (jbase + 63 > qbase + wbase) {
                const int grow0 = qbase + wbase + gq;
                #pragma unroll
                for (int j = 0; j < 8; ++j) {
                    int gc = jbase + j * 8 + 2 * tg;
                    if (gc     > grow0)     s[j][0] = -1e30f;
                    if (gc + 1 > grow0)     s[j][1] = -1e30f;
                    if (gc     > grow0 + 8) s[j][2] = -1e30f;
                    if (gc + 1 > grow0 + 8) s[j][3] = -1e30f;
                }
            }

            // online softmax in registers
            float tm0 = -INFINITY, tm1 = -INFINITY;
            #pragma unroll
            for (int j = 0; j < 8; ++j) {
                tm0 = fmaxf(tm0, fmaxf(s[j][0], s[j][1]));
                tm1 = fmaxf(tm1, fmaxf(s[j][2], s[j][3]));
            }
            tm0 = fmaxf(tm0, __shfl_xor_sync(0xffffffffu, tm0, 1));
            tm0 = fmaxf(tm0, __shfl_xor_sync(0xffffffffu, tm0, 2));
            tm1 = fmaxf(tm1, __shfl_xor_sync(0xffffffffu, tm1, 1));
            tm1 = fmaxf(tm1, __shfl_xor_sync(0xffffffffu, tm1, 2));

            float mn0 = fmaxf(m0r, tm0), mn1 = fmaxf(m1r, tm1);
            float cf0 = __expf(m0r - mn0), cf1 = __expf(m1r - mn1);
            m0r = mn0; m1r = mn1;

            float sum0 = 0.f, sum1 = 0.f;
            #pragma unroll
            for (int j = 0; j < 8; ++j) {
                float p0 = __expf(s[j][0] - mn0);
                float p1 = __expf(s[j][1] - mn0);
                float p2 = __expf(s[j][2] - mn1);
                float p3 = __expf(s[j][3] - mn1);
                sum0 += p0 + p1; sum1 += p2 + p3;
                s[j][0] = f2tf32(p0); s[j][1] = f2tf32(p1);
                s[j][2] = f2tf32(p2); s[j][3] = f2tf32(p3);
            }
            sum0 += __shfl_xor_sync(0xffffffffu, sum0, 1);
            sum0 += __shfl_xor_sync(0xffffffffu, sum0, 2);
            sum1 += __shfl_xor_sync(0xffffffffu, sum1, 1);
            sum1 += __shfl_xor_sync(0xffffffffu, sum1, 2);
            l0r = l0r * cf0 + sum0;
            l1r = l1r * cf1 + sum1;

            #pragma unroll
            for (int j = 0; j < 8; ++j) {
                o[j][0] *= cf0; o[j][1] *= cf0;
                o[j][2] *= cf1; o[j][3] *= cf1;
            }

            // write P to Ss (per-warp rows)
            {
                const int r0 = wbase + gq, r1 = r0 + 8;
                #pragma unroll
                for (int j = 0; j < 8; ++j) {
                    const int c = j * 8 + 2 * tg;
                    *reinterpret_cast<float2*>(&Ss[r0 * PQ + c]) = make_float2(s[j][0], s[j][1]);
                    *reinterpret_cast<float2*>(&Ss[r1 * PQ + c]) = make_float2(s[j][2], s[j][3]);
                }
            }
            __syncwarp();

            // O += P @ V
            #pragma unroll
            for (int kk = 0; kk < 8; ++kk) {
                const int k = kk << 3;
                uint32_t afr[4];
                const int r = wbase + gq;
                const int c = k + tg;
                afr[0] = __float_as_uint(Ss[r * PQ + c]);
                afr[1] = __float_as_uint(Ss[(r + 8) * PQ + c]);
                afr[2] = __float_as_uint(Ss[r * PQ + c + 4]);
                afr[3] = __float_as_uint(Ss[(r + 8) * PQ + c + 4]);
                #pragma unroll
                for (int j = 0; j < 8; ++j) {
                    uint32_t bfr[2];
                    bfr[0] = __float_as_uint(Vs[(k + tg) * PV + j * 8 + gq]);
                    bfr[1] = __float_as_uint(Vs[(k + tg + 4) * PV + j * 8 + gq]);
                    mma_tf32(o[j], afr, bfr);
                }
            }
        }
        __syncthreads();
    }

    // epilogue (tf32-rounded — feeds O-proj GEMM)
    const float inv0 = 1.f / l0r, inv1 = 1.f / l1r;
    const int grow0 = qbase + wbase + gq;
    const size_t obase = ((size_t)b * SEQ + grow0) * D_MODEL + h * HDIM;
    #pragma unroll
    for (int j = 0; j < 8; ++j) {
        const int c = j * 8 + 2 * tg;
        *reinterpret_cast<float2*>(ctx + obase + c) =
            make_float2(f2tf32(o[j][0] * inv0), f2tf32(o[j][1] * inv0));
        *reinterpret_cast<float2*>(ctx + obase + (size_t)8 * D_MODEL + c) =
            make_float2(f2tf32(o[j][2] * inv1), f2tf32(o[j][3] * inv1));
    }
}

// -------------------- launch --------------------
extern "C" void kernel_launch(void* const* d_in, const int* in_sizes, int n_in,
                              void* d_out, int out_size)
{
    const float* x     = (const float*)d_in[0];
    const float* w_qkv = (const float*)d_in[1];
    const float* b_qkv = (const float*)d_in[2];
    const float* w_o   = (const float*)d_in[3];
    const float* b_o   = (const float*)d_in[4];
    const float* g1    = (const float*)d_in[5];
    const float* be1   = (const float*)d_in[6];
    const float* g2    = (const float*)d_in[7];
    const float* be2   = (const float*)d_in[8];
    const float* w1    = (const float*)d_in[9];
    const float* b1    = (const float*)d_in[10];
    const float* w2    = (const float*)d_in[11];
    const float* b2    = (const float*)d_in[12];
    float* out = (float*)d_out;

    float *p_nx, *p_qkv, *p_ctx, *p_x1, *p_h;
    float *p_wqkv, *p_wo, *p_w1, *p_w2;
    cudaGetSymbolAddress((void**)&p_nx,   g_nx);
    cudaGetSymbolAddress((void**)&p_qkv,  g_qkv);
    cudaGetSymbolAddress((void**)&p_ctx,  g_ctx);
    cudaGetSymbolAddress((void**)&p_x1,   g_x1);
    cudaGetSymbolAddress((void**)&p_h,    g_h);
    cudaGetSymbolAddress((void**)&p_wqkv, g_wqkv);
    cudaGetSymbolAddress((void**)&p_wo,   g_wo);
    cudaGetSymbolAddress((void**)&p_w1,   g_w1);
    cudaGetSymbolAddress((void**)&p_w2,   g_w2);

    static const int GEMM_SMEM  = STAGES * SSZ * (int)sizeof(float);
    static const int FLASH_SMEM = (QTILE * PQ + 2 * KVSZ + QTILE * PQ) * (int)sizeof(float); // ~206 KB
    cudaFuncSetAttribute(tgemm_k<0,1>, cudaFuncAttributeMaxDynamicSharedMemorySize, GEMM_SMEM);
    cudaFuncSetAttribute(tgemm_k<1,1>, cudaFuncAttributeMaxDynamicSharedMemorySize, GEMM_SMEM);
    cudaFuncSetAttribute(tgemm_k<2,0>, cudaFuncAttributeMaxDynamicSharedMemorySize, GEMM_SMEM);
    cudaFuncSetAttribute(flash_attn_k, cudaFuncAttributeMaxDynamicSharedMemorySize, FLASH_SMEM);

    // 0) all weights -> tf32 (one launch)
    cvt_all_k<<<1184, 256>>>(w_qkv, w_o, w1, w2, p_wqkv, p_wo, p_w1, p_w2);

    // 1) nx = LN1(x)
    ln_kernel<<<NROWS, 256>>>(x, g1, be1, p_nx);

    // 2) qkv = nx @ w_qkv + b_qkv
    tgemm_k<0,1><<<dim3(3 * D_MODEL / 128, NROWS / 128), 256, GEMM_SMEM>>>(
        p_nx, p_wqkv, b_qkv, nullptr, p_qkv, NROWS, 3 * D_MODEL, D_MODEL);

    // 3) ctx = causal attention(q,k,v)
    flash_attn_k<<<dim3(SEQ / QTILE, NHEAD, BATCH), 512, FLASH_SMEM>>>(p_qkv, p_ctx);

    // 4) x1 = x + ctx @ w_o + b_o
    tgemm_k<2,0><<<dim3(D_MODEL / 128, NROWS / 128), 256, GEMM_SMEM>>>(
        p_ctx, p_wo, b_o, x, p_x1, NROWS, D_MODEL, D_MODEL);

    // 5) nx = LN2(x1)
    ln_kernel<<<NROWS, 256>>>(p_x1, g2, be2, p_nx);

    // 6) h = gelu(nx @ w1 + b1)
    tgemm_k<1,1><<<dim3(D_MID / 128, NROWS / 128), 256, GEMM_SMEM>>>(
        p_nx, p_w1, b1, nullptr, p_h, NROWS, D_MID, D_MODEL);

    // 7) out = x1 + h @ w2 + b2
    tgemm_k<2,0><<<dim3(D_MODEL / 128, NROWS / 128), 256, GEMM_SMEM>>>(
        p_h, p_w2, b2, p_x1, out, NROWS, D_MODEL, D_MID);
}